// round 1
// baseline (speedup 1.0000x reference)
#include <cuda_runtime.h>
#include <math.h>

namespace {
constexpr int D = 128;
constexpr int R = 32;          // rows per block
constexpr int NTHREADS = 256;
// smem layout (floats): smA,smV,smL (3*R*D) | smG (3*R*D) | smFus (R*384) | smH (96*64) | attw (128) | scal (R*16)
constexpr int SMEM_FLOATS = 3 * R * D + 3 * R * D + R * 384 + 96 * 64 + 128 + R * 16;
}

__device__ __forceinline__ float warp_sum(float x) {
#pragma unroll
    for (int o = 16; o > 0; o >>= 1) x += __shfl_xor_sync(0xffffffffu, x, o);
    return x;
}
__device__ __forceinline__ float warp_max(float x) {
#pragma unroll
    for (int o = 16; o > 0; o >>= 1) x = fmaxf(x, __shfl_xor_sync(0xffffffffu, x, o));
    return x;
}

// One "gf-style" MLP stage over 3 (x,y) pairs of 32 rows each:
//   H[96][64]  = leaky_relu( concat(x,y)[96][256] @ W1 + b1 )
//   G[96][128] = tanh( H @ W2 + b2 )
// MODE 0: store G into smG (3 buffers of [32][128])
// MODE 1: trimodal accumulate: smFus[r][256+j] += tanh( n2[N2BASE+p] * G )
template <int MODE, int N2BASE>
__device__ __forceinline__ void mlp_stage(
    const float* __restrict__ W1, const float* __restrict__ b1,
    const float* __restrict__ W2, const float* __restrict__ b2,
    const float* sx0, const float* sy0,
    const float* sx1, const float* sy1,
    const float* sx2, const float* sy2,
    float* smH, float* smG, float* smFus, const float* smScal)
{
    const int tid = threadIdx.x;
    const int rg = tid >> 4;   // 16 row groups of 6 rows
    const int cg = tid & 15;   // 16 col groups

    const float* srcX[3] = {sx0, sx1, sx2};
    const float* srcY[3] = {sy0, sy1, sy2};

    // ---- GEMM1: [96 x 256] @ [256 x 64], 6 rows x 4 cols per thread ----
    {
        const float* xA[6];
        const float* xB[6];
#pragma unroll
        for (int i = 0; i < 6; ++i) {
            int m = rg * 6 + i;
            int p = m >> 5;
            int r = m & 31;
            xA[i] = srcX[p] + r * D;
            xB[i] = srcY[p] + r * D;
        }
        float4 bb = __ldg((const float4*)(b1 + cg * 4));
        float acc[6][4];
#pragma unroll
        for (int i = 0; i < 6; ++i) {
            acc[i][0] = bb.x; acc[i][1] = bb.y; acc[i][2] = bb.z; acc[i][3] = bb.w;
        }
#pragma unroll 4
        for (int k = 0; k < 128; ++k) {
            float4 w = __ldg((const float4*)(W1 + k * 64 + cg * 4));
#pragma unroll
            for (int i = 0; i < 6; ++i) {
                float x = xA[i][k];
                acc[i][0] = fmaf(x, w.x, acc[i][0]);
                acc[i][1] = fmaf(x, w.y, acc[i][1]);
                acc[i][2] = fmaf(x, w.z, acc[i][2]);
                acc[i][3] = fmaf(x, w.w, acc[i][3]);
            }
        }
#pragma unroll 4
        for (int k = 0; k < 128; ++k) {
            float4 w = __ldg((const float4*)(W1 + (k + 128) * 64 + cg * 4));
#pragma unroll
            for (int i = 0; i < 6; ++i) {
                float x = xB[i][k];
                acc[i][0] = fmaf(x, w.x, acc[i][0]);
                acc[i][1] = fmaf(x, w.y, acc[i][1]);
                acc[i][2] = fmaf(x, w.z, acc[i][2]);
                acc[i][3] = fmaf(x, w.w, acc[i][3]);
            }
        }
#pragma unroll
        for (int i = 0; i < 6; ++i) {
            int m = rg * 6 + i;
#pragma unroll
            for (int j = 0; j < 4; ++j) {
                float h = acc[i][j];
                h = (h >= 0.0f) ? h : 0.2f * h;   // leaky_relu(0.2)
                smH[m * 64 + cg * 4 + j] = h;
            }
        }
    }
    __syncthreads();
    // ---- GEMM2: [96 x 64] @ [64 x 128], 6 rows x 8 cols per thread ----
    {
        float acc[6][8];
        float4 b20 = __ldg((const float4*)(b2 + cg * 8));
        float4 b21 = __ldg((const float4*)(b2 + cg * 8 + 4));
#pragma unroll
        for (int i = 0; i < 6; ++i) {
            acc[i][0] = b20.x; acc[i][1] = b20.y; acc[i][2] = b20.z; acc[i][3] = b20.w;
            acc[i][4] = b21.x; acc[i][5] = b21.y; acc[i][6] = b21.z; acc[i][7] = b21.w;
        }
#pragma unroll 4
        for (int k = 0; k < 64; ++k) {
            float4 w0 = __ldg((const float4*)(W2 + k * 128 + cg * 8));
            float4 w1 = __ldg((const float4*)(W2 + k * 128 + cg * 8 + 4));
#pragma unroll
            for (int i = 0; i < 6; ++i) {
                float x = smH[(rg * 6 + i) * 64 + k];
                acc[i][0] = fmaf(x, w0.x, acc[i][0]);
                acc[i][1] = fmaf(x, w0.y, acc[i][1]);
                acc[i][2] = fmaf(x, w0.z, acc[i][2]);
                acc[i][3] = fmaf(x, w0.w, acc[i][3]);
                acc[i][4] = fmaf(x, w1.x, acc[i][4]);
                acc[i][5] = fmaf(x, w1.y, acc[i][5]);
                acc[i][6] = fmaf(x, w1.z, acc[i][6]);
                acc[i][7] = fmaf(x, w1.w, acc[i][7]);
            }
        }
#pragma unroll
        for (int i = 0; i < 6; ++i) {
            int m = rg * 6 + i;
            int p = m >> 5;
            int r = m & 31;
            if (MODE == 0) {
#pragma unroll
                for (int j = 0; j < 8; ++j)
                    smG[p * (R * D) + r * D + cg * 8 + j] = tanhf(acc[i][j]);
            } else {
                float nv = smScal[r * 16 + 9 + N2BASE + p];
#pragma unroll
                for (int j = 0; j < 8; ++j)
                    atomicAdd(&smFus[r * 384 + 256 + cg * 8 + j], tanhf(nv * tanhf(acc[i][j])));
            }
        }
    }
}

__global__ void __launch_bounds__(NTHREADS, 1)
graphfusion_kernel(
    const float* __restrict__ Lm, const float* __restrict__ Am, const float* __restrict__ Vm,
    const float* __restrict__ att_w, const float* __restrict__ att_b,
    const float* __restrict__ gf_w1, const float* __restrict__ gf_b1,
    const float* __restrict__ gf_w2, const float* __restrict__ gf_b2,
    const float* __restrict__ gf2_w1, const float* __restrict__ gf2_b1,
    const float* __restrict__ gf2_w2, const float* __restrict__ gf2_b2,
    const float* __restrict__ ll_w1, const float* __restrict__ ll_b1,
    const float* __restrict__ ll_w2, const float* __restrict__ ll_b2,
    const float* __restrict__ ll_w3, const float* __restrict__ ll_b3,
    float* __restrict__ out)
{
    extern __shared__ float sm[];
    float* smA    = sm;                 // softmax(a) [32][128]
    float* smV    = smA + R * D;
    float* smL    = smV + R * D;
    float* smG    = smL + R * D;        // gav/gal/gvl -> a_v/a_l/v_l, 3x[32][128]
    float* smFus  = smG + 3 * R * D;    // fusion [32][384]
    float* smH    = smFus + R * 384;    // hidden [96][64]  (rows 32..63 reused as H2)
    float* smAttw = smH + 96 * 64;      // [128]
    float* smScal = smAttw + D;         // [32][16]: n0,n1,n2, sav,sal,svl, sa,sv,sl, n2[0..5]

    const int tid = threadIdx.x;
    const int lane = tid & 31;
    const int wid = tid >> 5;

    if (tid < D) smAttw[tid] = att_w[tid];
    __syncthreads();
    const float attb = __ldg(att_b);

    // ================= Phase A: per-row scalars + softmaxes + unimodal =================
    {
        float4 aw = ((const float4*)smAttw)[lane];
#pragma unroll
        for (int rr = 0; rr < 4; ++rr) {
            int r = wid * 4 + rr;
            size_t grow = (size_t)blockIdx.x * R + r;
            float4 a4 = ((const float4*)(Am + grow * D))[lane];
            float4 v4 = ((const float4*)(Vm + grow * D))[lane];
            float4 l4 = ((const float4*)(Lm + grow * D))[lane];

            float sa = tanhf(warp_sum(a4.x * aw.x + a4.y * aw.y + a4.z * aw.z + a4.w * aw.w) + attb);
            float sv = tanhf(warp_sum(v4.x * aw.x + v4.y * aw.y + v4.z * aw.z + v4.w * aw.w) + attb);
            float sl = tanhf(warp_sum(l4.x * aw.x + l4.y * aw.y + l4.z * aw.z + l4.w * aw.w) + attb);

            float4 u;
            u.x = (sa * a4.x + sv * v4.x + sl * l4.x) * (1.0f / 3.0f);
            u.y = (sa * a4.y + sv * v4.y + sl * l4.y) * (1.0f / 3.0f);
            u.z = (sa * a4.z + sv * v4.z + sl * l4.z) * (1.0f / 3.0f);
            u.w = (sa * a4.w + sv * v4.w + sl * l4.w) * (1.0f / 3.0f);
            ((float4*)(smFus + r * 384))[lane] = u;   // unimodal

            // softmax(a), softmax(v), softmax(l)
            float ma = warp_max(fmaxf(fmaxf(a4.x, a4.y), fmaxf(a4.z, a4.w)));
            float4 ea = make_float4(__expf(a4.x - ma), __expf(a4.y - ma), __expf(a4.z - ma), __expf(a4.w - ma));
            float ia = 1.0f / warp_sum(ea.x + ea.y + ea.z + ea.w);
            float4 pa = make_float4(ea.x * ia, ea.y * ia, ea.z * ia, ea.w * ia);

            float mv = warp_max(fmaxf(fmaxf(v4.x, v4.y), fmaxf(v4.z, v4.w)));
            float4 ev = make_float4(__expf(v4.x - mv), __expf(v4.y - mv), __expf(v4.z - mv), __expf(v4.w - mv));
            float iv = 1.0f / warp_sum(ev.x + ev.y + ev.z + ev.w);
            float4 pv = make_float4(ev.x * iv, ev.y * iv, ev.z * iv, ev.w * iv);

            float ml = warp_max(fmaxf(fmaxf(l4.x, l4.y), fmaxf(l4.z, l4.w)));
            float4 el = make_float4(__expf(l4.x - ml), __expf(l4.y - ml), __expf(l4.z - ml), __expf(l4.w - ml));
            float il = 1.0f / warp_sum(el.x + el.y + el.z + el.w);
            float4 pl = make_float4(el.x * il, el.y * il, el.z * il, el.w * il);

            ((float4*)(smA + r * D))[lane] = pa;
            ((float4*)(smV + r * D))[lane] = pv;
            ((float4*)(smL + r * D))[lane] = pl;

            float dav = warp_sum(pa.x * pv.x + pa.y * pv.y + pa.z * pv.z + pa.w * pv.w);
            float dal = warp_sum(pa.x * pl.x + pa.y * pl.y + pa.z * pl.z + pa.w * pl.w);
            float dvl = warp_sum(pv.x * pl.x + pv.y * pl.y + pv.z * pl.z + pv.w * pl.w);

            float sav = (sa + sv) / (dav + 0.5f);
            float sal = (sa + sl) / (dal + 0.5f);
            float svl = (sl + sv) / (dvl + 0.5f);
            float mx = fmaxf(sav, fmaxf(sal, svl));
            float e0 = __expf(sav - mx), e1 = __expf(sal - mx), e2 = __expf(svl - mx);
            float is = 1.0f / (e0 + e1 + e2);
            if (lane == 0) {
                float* sc = smScal + r * 16;
                sc[0] = e0 * is; sc[1] = e1 * is; sc[2] = e2 * is;
                sc[3] = sav; sc[4] = sal; sc[5] = svl;
                sc[6] = sa;  sc[7] = sv;  sc[8] = sl;
            }
        }
    }
    __syncthreads();

    // ================= gf stage: gav=gf(a,v), gal=gf(a,l), gvl=gf(v,l) =================
    mlp_stage<0, 0>(gf_w1, gf_b1, gf_w2, gf_b2,
                    smA, smV, smA, smL, smV, smL,
                    smH, smG, smFus, smScal);
    __syncthreads();

    // ============ Phase C: softmax(g)'s dots, n2, a_v/a_l/v_l, bimodal ============
    {
#pragma unroll
        for (int rr = 0; rr < 4; ++rr) {
            int r = wid * 4 + rr;
            float4 g0 = ((const float4*)(smG + 0 * R * D + r * D))[lane];   // gav
            float4 g1 = ((const float4*)(smG + 1 * R * D + r * D))[lane];   // gal
            float4 g2 = ((const float4*)(smG + 2 * R * D + r * D))[lane];   // gvl
            float4 pa = ((const float4*)(smA + r * D))[lane];
            float4 pv = ((const float4*)(smV + r * D))[lane];
            float4 pl = ((const float4*)(smL + r * D))[lane];

            float m0 = warp_max(fmaxf(fmaxf(g0.x, g0.y), fmaxf(g0.z, g0.w)));
            float m1 = warp_max(fmaxf(fmaxf(g1.x, g1.y), fmaxf(g1.z, g1.w)));
            float m2 = warp_max(fmaxf(fmaxf(g2.x, g2.y), fmaxf(g2.z, g2.w)));
            float4 e0 = make_float4(__expf(g0.x - m0), __expf(g0.y - m0), __expf(g0.z - m0), __expf(g0.w - m0));
            float4 e1 = make_float4(__expf(g1.x - m1), __expf(g1.y - m1), __expf(g1.z - m1), __expf(g1.w - m1));
            float4 e2 = make_float4(__expf(g2.x - m2), __expf(g2.y - m2), __expf(g2.z - m2), __expf(g2.w - m2));
            float i0 = 1.0f / warp_sum(e0.x + e0.y + e0.z + e0.w);
            float i1 = 1.0f / warp_sum(e1.x + e1.y + e1.z + e1.w);
            float i2 = 1.0f / warp_sum(e2.x + e2.y + e2.z + e2.w);

            float d01 = warp_sum(e0.x * e1.x + e0.y * e1.y + e0.z * e1.z + e0.w * e1.w);
            float d02 = warp_sum(e0.x * e2.x + e0.y * e2.y + e0.z * e2.z + e0.w * e2.w);
            float d12 = warp_sum(e1.x * e2.x + e1.y * e2.y + e1.z * e2.z + e1.w * e2.w);
            float d0l = warp_sum(e0.x * pl.x + e0.y * pl.y + e0.z * pl.z + e0.w * pl.w);
            float d1v = warp_sum(e1.x * pv.x + e1.y * pv.y + e1.z * pv.z + e1.w * pv.w);
            float d2a = warp_sum(e2.x * pa.x + e2.y * pa.y + e2.z * pa.z + e2.w * pa.w);

            const float* sc = smScal + r * 16;
            float sav = sc[3], sal = sc[4], svl = sc[5];
            float sa = sc[6], sv = sc[7], sl = sc[8];
            float t0 = (sav + svl) / (d02 * i0 * i2 + 0.5f);   // savvl
            float t1 = (sav + sal) / (d01 * i0 * i1 + 0.5f);   // saavl
            float t2 = (sal + svl) / (d12 * i1 * i2 + 0.5f);   // savll
            float t3 = (sav + sl)  / (d0l * i0 + 0.5f);        // savl
            float t4 = (sal + sv)  / (d1v * i1 + 0.5f);        // salv
            float t5 = (sa  + svl) / (d2a * i2 + 0.5f);        // svla
            float mm = fmaxf(fmaxf(fmaxf(t0, t1), fmaxf(t2, t3)), fmaxf(t4, t5));
            float q0 = __expf(t0 - mm), q1 = __expf(t1 - mm), q2 = __expf(t2 - mm);
            float q3 = __expf(t3 - mm), q4 = __expf(t4 - mm), q5 = __expf(t5 - mm);
            float qi = 1.0f / (q0 + q1 + q2 + q3 + q4 + q5);
            if (lane == 0) {
                float* scw = smScal + r * 16;
                scw[9] = q0 * qi; scw[10] = q1 * qi; scw[11] = q2 * qi;
                scw[12] = q3 * qi; scw[13] = q4 * qi; scw[14] = q5 * qi;
            }

            float n0 = sc[0], n1 = sc[1], n2v = sc[2];
            float4 av = make_float4(tanhf(n0 * g0.x), tanhf(n0 * g0.y), tanhf(n0 * g0.z), tanhf(n0 * g0.w));
            float4 al = make_float4(tanhf(n1 * g1.x), tanhf(n1 * g1.y), tanhf(n1 * g1.z), tanhf(n1 * g1.w));
            float4 vl = make_float4(tanhf(n2v * g2.x), tanhf(n2v * g2.y), tanhf(n2v * g2.z), tanhf(n2v * g2.w));
            ((float4*)(smG + 0 * R * D + r * D))[lane] = av;
            ((float4*)(smG + 1 * R * D + r * D))[lane] = al;
            ((float4*)(smG + 2 * R * D + r * D))[lane] = vl;
            float4 bm = make_float4(av.x + al.x + vl.x, av.y + al.y + vl.y,
                                    av.z + al.z + vl.z, av.w + al.w + vl.w);
            ((float4*)(smFus + r * 384 + 128))[lane] = bm;              // bimodal
            ((float4*)(smFus + r * 384 + 256))[lane] = make_float4(0.f, 0.f, 0.f, 0.f);  // trimodal init
        }
    }
    __syncthreads();

    // ================= gf2 stages (trimodal) =================
    float* G0 = smG;               // a_v
    float* G1 = smG + R * D;       // a_l
    float* G2 = smG + 2 * R * D;   // v_l
    // pairs 0..2: (a_v,v_l), (a_v,a_l), (v_l,a_l)
    mlp_stage<1, 0>(gf2_w1, gf2_b1, gf2_w2, gf2_b2,
                    G0, G2, G0, G1, G2, G1,
                    smH, smG, smFus, smScal);
    __syncthreads();
    // pairs 3..5: (a_v,l), (a_l,v), (v_l,a)
    mlp_stage<1, 3>(gf2_w1, gf2_b1, gf2_w2, gf2_b2,
                    G0, smL, G1, smV, G2, smA,
                    smH, smG, smFus, smScal);
    __syncthreads();

    // ================= ll chain: fusion[32][384] -> 64 -> 64 -> 128 =================
    {
        const int rg = tid >> 4, cg = tid & 15;
        const int r0 = rg * 2;
        float4 bb = __ldg((const float4*)(ll_b1 + cg * 4));
        float acc[2][4];
        acc[0][0] = bb.x; acc[0][1] = bb.y; acc[0][2] = bb.z; acc[0][3] = bb.w;
        acc[1][0] = bb.x; acc[1][1] = bb.y; acc[1][2] = bb.z; acc[1][3] = bb.w;
#pragma unroll 4
        for (int k = 0; k < 384; ++k) {
            float4 w = __ldg((const float4*)(ll_w1 + k * 64 + cg * 4));
            float x0 = smFus[r0 * 384 + k];
            float x1 = smFus[r0 * 384 + 384 + k];
            acc[0][0] = fmaf(x0, w.x, acc[0][0]); acc[0][1] = fmaf(x0, w.y, acc[0][1]);
            acc[0][2] = fmaf(x0, w.z, acc[0][2]); acc[0][3] = fmaf(x0, w.w, acc[0][3]);
            acc[1][0] = fmaf(x1, w.x, acc[1][0]); acc[1][1] = fmaf(x1, w.y, acc[1][1]);
            acc[1][2] = fmaf(x1, w.z, acc[1][2]); acc[1][3] = fmaf(x1, w.w, acc[1][3]);
        }
#pragma unroll
        for (int i = 0; i < 2; ++i)
#pragma unroll
            for (int j = 0; j < 4; ++j)
                smH[(r0 + i) * 64 + cg * 4 + j] = tanhf(acc[i][j]);
    }
    __syncthreads();
    {
        const int rg = tid >> 4, cg = tid & 15;
        const int r0 = rg * 2;
        float4 bb = __ldg((const float4*)(ll_b2 + cg * 4));
        float acc[2][4];
        acc[0][0] = bb.x; acc[0][1] = bb.y; acc[0][2] = bb.z; acc[0][3] = bb.w;
        acc[1][0] = bb.x; acc[1][1] = bb.y; acc[1][2] = bb.z; acc[1][3] = bb.w;
#pragma unroll 4
        for (int k = 0; k < 64; ++k) {
            float4 w = __ldg((const float4*)(ll_w2 + k * 64 + cg * 4));
            float x0 = smH[r0 * 64 + k];
            float x1 = smH[(r0 + 1) * 64 + k];
            acc[0][0] = fmaf(x0, w.x, acc[0][0]); acc[0][1] = fmaf(x0, w.y, acc[0][1]);
            acc[0][2] = fmaf(x0, w.z, acc[0][2]); acc[0][3] = fmaf(x0, w.w, acc[0][3]);
            acc[1][0] = fmaf(x1, w.x, acc[1][0]); acc[1][1] = fmaf(x1, w.y, acc[1][1]);
            acc[1][2] = fmaf(x1, w.z, acc[1][2]); acc[1][3] = fmaf(x1, w.w, acc[1][3]);
        }
#pragma unroll
        for (int i = 0; i < 2; ++i)
#pragma unroll
            for (int j = 0; j < 4; ++j)
                smH[2048 + (r0 + i) * 64 + cg * 4 + j] = tanhf(acc[i][j]);  // H2 region
    }
    __syncthreads();
    {
        const int rg = tid >> 5, cg = tid & 31;   // 8 row groups x 4 rows, 32 col groups x 4 cols
        float4 bb = __ldg((const float4*)(ll_b3 + cg * 4));
        float acc[4][4];
#pragma unroll
        for (int i = 0; i < 4; ++i) {
            acc[i][0] = bb.x; acc[i][1] = bb.y; acc[i][2] = bb.z; acc[i][3] = bb.w;
        }
#pragma unroll 4
        for (int k = 0; k < 64; ++k) {
            float4 w = __ldg((const float4*)(ll_w3 + k * 128 + cg * 4));
#pragma unroll
            for (int i = 0; i < 4; ++i) {
                float x = smH[2048 + (rg * 4 + i) * 64 + k];
                acc[i][0] = fmaf(x, w.x, acc[i][0]);
                acc[i][1] = fmaf(x, w.y, acc[i][1]);
                acc[i][2] = fmaf(x, w.z, acc[i][2]);
                acc[i][3] = fmaf(x, w.w, acc[i][3]);
            }
        }
#pragma unroll
        for (int i = 0; i < 4; ++i) {
            int r = rg * 4 + i;
            size_t grow = (size_t)blockIdx.x * R + r;
            float4 o = make_float4(tanhf(acc[i][0]), tanhf(acc[i][1]), tanhf(acc[i][2]), tanhf(acc[i][3]));
            ((float4*)(out + grow * D))[cg] = o;
        }
    }
}

extern "C" void kernel_launch(void* const* d_in, const int* in_sizes, int n_in,
                              void* d_out, int out_size) {
    const float* Lm     = (const float*)d_in[0];
    const float* Am     = (const float*)d_in[1];
    const float* Vm     = (const float*)d_in[2];
    const float* att_w  = (const float*)d_in[3];
    const float* att_b  = (const float*)d_in[4];
    const float* gf_w1  = (const float*)d_in[5];
    const float* gf_b1  = (const float*)d_in[6];
    const float* gf_w2  = (const float*)d_in[7];
    const float* gf_b2  = (const float*)d_in[8];
    const float* gf2_w1 = (const float*)d_in[9];
    const float* gf2_b1 = (const float*)d_in[10];
    const float* gf2_w2 = (const float*)d_in[11];
    const float* gf2_b2 = (const float*)d_in[12];
    const float* ll_w1  = (const float*)d_in[13];
    const float* ll_b1  = (const float*)d_in[14];
    const float* ll_w2  = (const float*)d_in[15];
    const float* ll_b2  = (const float*)d_in[16];
    const float* ll_w3  = (const float*)d_in[17];
    const float* ll_b3  = (const float*)d_in[18];

    int nrows = in_sizes[0] / D;
    int grid = nrows / R;
    size_t smem = (size_t)SMEM_FLOATS * sizeof(float);
    cudaFuncSetAttribute(graphfusion_kernel,
                         cudaFuncAttributeMaxDynamicSharedMemorySize, (int)smem);
    graphfusion_kernel<<<grid, NTHREADS, smem>>>(
        Lm, Am, Vm, att_w, att_b,
        gf_w1, gf_b1, gf_w2, gf_b2,
        gf2_w1, gf2_b1, gf2_w2, gf2_b2,
        ll_w1, ll_b1, ll_w2, ll_b2, ll_w3, ll_b3,
        (float*)d_out);
}

// round 2
// speedup vs baseline: 1.2777x; 1.2777x over previous
#include <cuda_runtime.h>
#include <math.h>

namespace {
constexpr int D = 128;
constexpr int R = 32;          // rows per block
constexpr int NTHREADS = 512;
// smem layout (floats): smA,smV,smL (3*R*D) | smG (3*R*D) | smFus (R*384) | smH (96*64) | attw (128) | scal (R*16)
constexpr int SMEM_FLOATS = 3 * R * D + 3 * R * D + R * 384 + 96 * 64 + 128 + R * 16;
}

__device__ __forceinline__ float warp_sum(float x) {
#pragma unroll
    for (int o = 16; o > 0; o >>= 1) x += __shfl_xor_sync(0xffffffffu, x, o);
    return x;
}
__device__ __forceinline__ float warp_max(float x) {
#pragma unroll
    for (int o = 16; o > 0; o >>= 1) x = fmaxf(x, __shfl_xor_sync(0xffffffffu, x, o));
    return x;
}
// Fast tanh via MUFU (sm_75+). Max rel err ~2^-11 — used for intermediates only.
__device__ __forceinline__ float tanh_fast(float x) {
    float y;
    asm("tanh.approx.f32 %0, %1;" : "=f"(y) : "f"(x));
    return y;
}

// One "gf-style" MLP stage over 3 (x,y) pairs of 32 rows each (96 rows total):
//   H[96][64]  = leaky_relu( concat(x,y)[96][256] @ W1 + b1 )
//   G[96][128] = tanh( H @ W2 + b2 )
// 512 threads: rg=tid>>4 (32 groups x 3 rows), cg=tid&15.
// MODE 0: store G into smG (3 buffers of [32][128])
// MODE 1: trimodal accumulate: smFus[r][256+j] += tanh( n2[N2BASE+p] * G )
template <int MODE, int N2BASE>
__device__ __forceinline__ void mlp_stage(
    const float* __restrict__ W1, const float* __restrict__ b1,
    const float* __restrict__ W2, const float* __restrict__ b2,
    const float* sx0, const float* sy0,
    const float* sx1, const float* sy1,
    const float* sx2, const float* sy2,
    float* smH, float* smG, float* smFus, const float* smScal)
{
    const int tid = threadIdx.x;
    const int rg = tid >> 4;   // 32 row groups of 3 rows
    const int cg = tid & 15;   // 16 col groups

    const float* srcX[3] = {sx0, sx1, sx2};
    const float* srcY[3] = {sy0, sy1, sy2};

    // ---- GEMM1: [96 x 256] @ [256 x 64], 3 rows x 4 cols per thread ----
    {
        const float4* xa4[3];
        const float4* xb4[3];
#pragma unroll
        for (int i = 0; i < 3; ++i) {
            int m = rg * 3 + i;
            int p = m >> 5;
            int r = m & 31;
            xa4[i] = (const float4*)(srcX[p] + r * D);
            xb4[i] = (const float4*)(srcY[p] + r * D);
        }
        float4 bb = __ldg((const float4*)(b1 + cg * 4));
        float acc[3][4];
#pragma unroll
        for (int i = 0; i < 3; ++i) {
            acc[i][0] = bb.x; acc[i][1] = bb.y; acc[i][2] = bb.z; acc[i][3] = bb.w;
        }
#pragma unroll 2
        for (int k4 = 0; k4 < 32; ++k4) {
            const float* wb = W1 + (k4 * 4) * 64 + cg * 4;
            float4 w0 = __ldg((const float4*)(wb));
            float4 w1 = __ldg((const float4*)(wb + 64));
            float4 w2 = __ldg((const float4*)(wb + 128));
            float4 w3 = __ldg((const float4*)(wb + 192));
#pragma unroll
            for (int i = 0; i < 3; ++i) {
                float4 x = xa4[i][k4];
                acc[i][0] = fmaf(x.x, w0.x, acc[i][0]); acc[i][1] = fmaf(x.x, w0.y, acc[i][1]);
                acc[i][2] = fmaf(x.x, w0.z, acc[i][2]); acc[i][3] = fmaf(x.x, w0.w, acc[i][3]);
                acc[i][0] = fmaf(x.y, w1.x, acc[i][0]); acc[i][1] = fmaf(x.y, w1.y, acc[i][1]);
                acc[i][2] = fmaf(x.y, w1.z, acc[i][2]); acc[i][3] = fmaf(x.y, w1.w, acc[i][3]);
                acc[i][0] = fmaf(x.z, w2.x, acc[i][0]); acc[i][1] = fmaf(x.z, w2.y, acc[i][1]);
                acc[i][2] = fmaf(x.z, w2.z, acc[i][2]); acc[i][3] = fmaf(x.z, w2.w, acc[i][3]);
                acc[i][0] = fmaf(x.w, w3.x, acc[i][0]); acc[i][1] = fmaf(x.w, w3.y, acc[i][1]);
                acc[i][2] = fmaf(x.w, w3.z, acc[i][2]); acc[i][3] = fmaf(x.w, w3.w, acc[i][3]);
            }
        }
#pragma unroll 2
        for (int k4 = 0; k4 < 32; ++k4) {
            const float* wb = W1 + (128 + k4 * 4) * 64 + cg * 4;
            float4 w0 = __ldg((const float4*)(wb));
            float4 w1 = __ldg((const float4*)(wb + 64));
            float4 w2 = __ldg((const float4*)(wb + 128));
            float4 w3 = __ldg((const float4*)(wb + 192));
#pragma unroll
            for (int i = 0; i < 3; ++i) {
                float4 x = xb4[i][k4];
                acc[i][0] = fmaf(x.x, w0.x, acc[i][0]); acc[i][1] = fmaf(x.x, w0.y, acc[i][1]);
                acc[i][2] = fmaf(x.x, w0.z, acc[i][2]); acc[i][3] = fmaf(x.x, w0.w, acc[i][3]);
                acc[i][0] = fmaf(x.y, w1.x, acc[i][0]); acc[i][1] = fmaf(x.y, w1.y, acc[i][1]);
                acc[i][2] = fmaf(x.y, w1.z, acc[i][2]); acc[i][3] = fmaf(x.y, w1.w, acc[i][3]);
                acc[i][0] = fmaf(x.z, w2.x, acc[i][0]); acc[i][1] = fmaf(x.z, w2.y, acc[i][1]);
                acc[i][2] = fmaf(x.z, w2.z, acc[i][2]); acc[i][3] = fmaf(x.z, w2.w, acc[i][3]);
                acc[i][0] = fmaf(x.w, w3.x, acc[i][0]); acc[i][1] = fmaf(x.w, w3.y, acc[i][1]);
                acc[i][2] = fmaf(x.w, w3.z, acc[i][2]); acc[i][3] = fmaf(x.w, w3.w, acc[i][3]);
            }
        }
#pragma unroll
        for (int i = 0; i < 3; ++i) {
            int m = rg * 3 + i;
#pragma unroll
            for (int j = 0; j < 4; ++j) {
                float h = acc[i][j];
                h = (h >= 0.0f) ? h : 0.2f * h;   // leaky_relu(0.2)
                smH[m * 64 + cg * 4 + j] = h;
            }
        }
    }
    __syncthreads();
    // ---- GEMM2: [96 x 64] @ [64 x 128], 3 rows x 8 cols per thread ----
    {
        float acc[3][8];
        float4 b20 = __ldg((const float4*)(b2 + cg * 8));
        float4 b21 = __ldg((const float4*)(b2 + cg * 8 + 4));
#pragma unroll
        for (int i = 0; i < 3; ++i) {
            acc[i][0] = b20.x; acc[i][1] = b20.y; acc[i][2] = b20.z; acc[i][3] = b20.w;
            acc[i][4] = b21.x; acc[i][5] = b21.y; acc[i][6] = b21.z; acc[i][7] = b21.w;
        }
#pragma unroll 2
        for (int k4 = 0; k4 < 16; ++k4) {
            const float* wb = W2 + (k4 * 4) * 128 + cg * 8;
            float4 wa0 = __ldg((const float4*)(wb));       float4 wb0 = __ldg((const float4*)(wb + 4));
            float4 wa1 = __ldg((const float4*)(wb + 128)); float4 wb1 = __ldg((const float4*)(wb + 132));
            float4 wa2 = __ldg((const float4*)(wb + 256)); float4 wb2 = __ldg((const float4*)(wb + 260));
            float4 wa3 = __ldg((const float4*)(wb + 384)); float4 wb3 = __ldg((const float4*)(wb + 388));
#pragma unroll
            for (int i = 0; i < 3; ++i) {
                float4 x = ((const float4*)(smH + (rg * 3 + i) * 64))[k4];
                acc[i][0] = fmaf(x.x, wa0.x, acc[i][0]); acc[i][1] = fmaf(x.x, wa0.y, acc[i][1]);
                acc[i][2] = fmaf(x.x, wa0.z, acc[i][2]); acc[i][3] = fmaf(x.x, wa0.w, acc[i][3]);
                acc[i][4] = fmaf(x.x, wb0.x, acc[i][4]); acc[i][5] = fmaf(x.x, wb0.y, acc[i][5]);
                acc[i][6] = fmaf(x.x, wb0.z, acc[i][6]); acc[i][7] = fmaf(x.x, wb0.w, acc[i][7]);
                acc[i][0] = fmaf(x.y, wa1.x, acc[i][0]); acc[i][1] = fmaf(x.y, wa1.y, acc[i][1]);
                acc[i][2] = fmaf(x.y, wa1.z, acc[i][2]); acc[i][3] = fmaf(x.y, wa1.w, acc[i][3]);
                acc[i][4] = fmaf(x.y, wb1.x, acc[i][4]); acc[i][5] = fmaf(x.y, wb1.y, acc[i][5]);
                acc[i][6] = fmaf(x.y, wb1.z, acc[i][6]); acc[i][7] = fmaf(x.y, wb1.w, acc[i][7]);
                acc[i][0] = fmaf(x.z, wa2.x, acc[i][0]); acc[i][1] = fmaf(x.z, wa2.y, acc[i][1]);
                acc[i][2] = fmaf(x.z, wa2.z, acc[i][2]); acc[i][3] = fmaf(x.z, wa2.w, acc[i][3]);
                acc[i][4] = fmaf(x.z, wb2.x, acc[i][4]); acc[i][5] = fmaf(x.z, wb2.y, acc[i][5]);
                acc[i][6] = fmaf(x.z, wb2.z, acc[i][6]); acc[i][7] = fmaf(x.z, wb2.w, acc[i][7]);
                acc[i][0] = fmaf(x.w, wa3.x, acc[i][0]); acc[i][1] = fmaf(x.w, wa3.y, acc[i][1]);
                acc[i][2] = fmaf(x.w, wa3.z, acc[i][2]); acc[i][3] = fmaf(x.w, wa3.w, acc[i][3]);
                acc[i][4] = fmaf(x.w, wb3.x, acc[i][4]); acc[i][5] = fmaf(x.w, wb3.y, acc[i][5]);
                acc[i][6] = fmaf(x.w, wb3.z, acc[i][6]); acc[i][7] = fmaf(x.w, wb3.w, acc[i][7]);
            }
        }
#pragma unroll
        for (int i = 0; i < 3; ++i) {
            int m = rg * 3 + i;
            int p = m >> 5;
            int r = m & 31;
            if (MODE == 0) {
#pragma unroll
                for (int j = 0; j < 8; ++j)
                    smG[p * (R * D) + r * D + cg * 8 + j] = tanh_fast(acc[i][j]);
            } else {
                float nv = smScal[r * 16 + 9 + N2BASE + p];
#pragma unroll
                for (int j = 0; j < 8; ++j)
                    atomicAdd(&smFus[r * 384 + 256 + cg * 8 + j], tanh_fast(nv * tanh_fast(acc[i][j])));
            }
        }
    }
}

__global__ void __launch_bounds__(NTHREADS, 1)
graphfusion_kernel(
    const float* __restrict__ Lm, const float* __restrict__ Am, const float* __restrict__ Vm,
    const float* __restrict__ att_w, const float* __restrict__ att_b,
    const float* __restrict__ gf_w1, const float* __restrict__ gf_b1,
    const float* __restrict__ gf_w2, const float* __restrict__ gf_b2,
    const float* __restrict__ gf2_w1, const float* __restrict__ gf2_b1,
    const float* __restrict__ gf2_w2, const float* __restrict__ gf2_b2,
    const float* __restrict__ ll_w1, const float* __restrict__ ll_b1,
    const float* __restrict__ ll_w2, const float* __restrict__ ll_b2,
    const float* __restrict__ ll_w3, const float* __restrict__ ll_b3,
    float* __restrict__ out)
{
    extern __shared__ float sm[];
    float* smA    = sm;                 // softmax(a) [32][128]
    float* smV    = smA + R * D;
    float* smL    = smV + R * D;
    float* smG    = smL + R * D;        // gav/gal/gvl -> a_v/a_l/v_l, 3x[32][128]
    float* smFus  = smG + 3 * R * D;    // fusion [32][384]
    float* smH    = smFus + R * 384;    // hidden [96][64]  (rows 32..63 reused as H2)
    float* smAttw = smH + 96 * 64;      // [128]
    float* smScal = smAttw + D;         // [32][16]

    const int tid = threadIdx.x;
    const int lane = tid & 31;
    const int wid = tid >> 5;           // 16 warps

    if (tid < D) smAttw[tid] = att_w[tid];
    __syncthreads();
    const float attb = __ldg(att_b);

    // ================= Phase A: per-row scalars + softmaxes + unimodal =================
    {
        float4 aw = ((const float4*)smAttw)[lane];
#pragma unroll
        for (int rr = 0; rr < 2; ++rr) {
            int r = wid * 2 + rr;
            size_t grow = (size_t)blockIdx.x * R + r;
            float4 a4 = ((const float4*)(Am + grow * D))[lane];
            float4 v4 = ((const float4*)(Vm + grow * D))[lane];
            float4 l4 = ((const float4*)(Lm + grow * D))[lane];

            float sa = tanh_fast(warp_sum(a4.x * aw.x + a4.y * aw.y + a4.z * aw.z + a4.w * aw.w) + attb);
            float sv = tanh_fast(warp_sum(v4.x * aw.x + v4.y * aw.y + v4.z * aw.z + v4.w * aw.w) + attb);
            float sl = tanh_fast(warp_sum(l4.x * aw.x + l4.y * aw.y + l4.z * aw.z + l4.w * aw.w) + attb);

            float4 u;
            u.x = (sa * a4.x + sv * v4.x + sl * l4.x) * (1.0f / 3.0f);
            u.y = (sa * a4.y + sv * v4.y + sl * l4.y) * (1.0f / 3.0f);
            u.z = (sa * a4.z + sv * v4.z + sl * l4.z) * (1.0f / 3.0f);
            u.w = (sa * a4.w + sv * v4.w + sl * l4.w) * (1.0f / 3.0f);
            ((float4*)(smFus + r * 384))[lane] = u;   // unimodal

            float ma = warp_max(fmaxf(fmaxf(a4.x, a4.y), fmaxf(a4.z, a4.w)));
            float4 ea = make_float4(__expf(a4.x - ma), __expf(a4.y - ma), __expf(a4.z - ma), __expf(a4.w - ma));
            float ia = 1.0f / warp_sum(ea.x + ea.y + ea.z + ea.w);
            float4 pa = make_float4(ea.x * ia, ea.y * ia, ea.z * ia, ea.w * ia);

            float mv = warp_max(fmaxf(fmaxf(v4.x, v4.y), fmaxf(v4.z, v4.w)));
            float4 ev = make_float4(__expf(v4.x - mv), __expf(v4.y - mv), __expf(v4.z - mv), __expf(v4.w - mv));
            float iv = 1.0f / warp_sum(ev.x + ev.y + ev.z + ev.w);
            float4 pv = make_float4(ev.x * iv, ev.y * iv, ev.z * iv, ev.w * iv);

            float ml = warp_max(fmaxf(fmaxf(l4.x, l4.y), fmaxf(l4.z, l4.w)));
            float4 el = make_float4(__expf(l4.x - ml), __expf(l4.y - ml), __expf(l4.z - ml), __expf(l4.w - ml));
            float il = 1.0f / warp_sum(el.x + el.y + el.z + el.w);
            float4 pl = make_float4(el.x * il, el.y * il, el.z * il, el.w * il);

            ((float4*)(smA + r * D))[lane] = pa;
            ((float4*)(smV + r * D))[lane] = pv;
            ((float4*)(smL + r * D))[lane] = pl;

            float dav = warp_sum(pa.x * pv.x + pa.y * pv.y + pa.z * pv.z + pa.w * pv.w);
            float dal = warp_sum(pa.x * pl.x + pa.y * pl.y + pa.z * pl.z + pa.w * pl.w);
            float dvl = warp_sum(pv.x * pl.x + pv.y * pl.y + pv.z * pl.z + pv.w * pl.w);

            float sav = (sa + sv) / (dav + 0.5f);
            float sal = (sa + sl) / (dal + 0.5f);
            float svl = (sl + sv) / (dvl + 0.5f);
            float mx = fmaxf(sav, fmaxf(sal, svl));
            float e0 = __expf(sav - mx), e1 = __expf(sal - mx), e2 = __expf(svl - mx);
            float is = 1.0f / (e0 + e1 + e2);
            if (lane == 0) {
                float* sc = smScal + r * 16;
                sc[0] = e0 * is; sc[1] = e1 * is; sc[2] = e2 * is;
                sc[3] = sav; sc[4] = sal; sc[5] = svl;
                sc[6] = sa;  sc[7] = sv;  sc[8] = sl;
            }
        }
    }
    __syncthreads();

    // ================= gf stage: gav=gf(a,v), gal=gf(a,l), gvl=gf(v,l) =================
    mlp_stage<0, 0>(gf_w1, gf_b1, gf_w2, gf_b2,
                    smA, smV, smA, smL, smV, smL,
                    smH, smG, smFus, smScal);
    __syncthreads();

    // ============ Phase C: softmax(g)'s dots, n2, a_v/a_l/v_l, bimodal ============
    {
#pragma unroll
        for (int rr = 0; rr < 2; ++rr) {
            int r = wid * 2 + rr;
            float4 g0 = ((const float4*)(smG + 0 * R * D + r * D))[lane];   // gav
            float4 g1 = ((const float4*)(smG + 1 * R * D + r * D))[lane];   // gal
            float4 g2 = ((const float4*)(smG + 2 * R * D + r * D))[lane];   // gvl
            float4 pa = ((const float4*)(smA + r * D))[lane];
            float4 pv = ((const float4*)(smV + r * D))[lane];
            float4 pl = ((const float4*)(smL + r * D))[lane];

            float m0 = warp_max(fmaxf(fmaxf(g0.x, g0.y), fmaxf(g0.z, g0.w)));
            float m1 = warp_max(fmaxf(fmaxf(g1.x, g1.y), fmaxf(g1.z, g1.w)));
            float m2 = warp_max(fmaxf(fmaxf(g2.x, g2.y), fmaxf(g2.z, g2.w)));
            float4 e0 = make_float4(__expf(g0.x - m0), __expf(g0.y - m0), __expf(g0.z - m0), __expf(g0.w - m0));
            float4 e1 = make_float4(__expf(g1.x - m1), __expf(g1.y - m1), __expf(g1.z - m1), __expf(g1.w - m1));
            float4 e2 = make_float4(__expf(g2.x - m2), __expf(g2.y - m2), __expf(g2.z - m2), __expf(g2.w - m2));
            float i0 = 1.0f / warp_sum(e0.x + e0.y + e0.z + e0.w);
            float i1 = 1.0f / warp_sum(e1.x + e1.y + e1.z + e1.w);
            float i2 = 1.0f / warp_sum(e2.x + e2.y + e2.z + e2.w);

            float d01 = warp_sum(e0.x * e1.x + e0.y * e1.y + e0.z * e1.z + e0.w * e1.w);
            float d02 = warp_sum(e0.x * e2.x + e0.y * e2.y + e0.z * e2.z + e0.w * e2.w);
            float d12 = warp_sum(e1.x * e2.x + e1.y * e2.y + e1.z * e2.z + e1.w * e2.w);
            float d0l = warp_sum(e0.x * pl.x + e0.y * pl.y + e0.z * pl.z + e0.w * pl.w);
            float d1v = warp_sum(e1.x * pv.x + e1.y * pv.y + e1.z * pv.z + e1.w * pv.w);
            float d2a = warp_sum(e2.x * pa.x + e2.y * pa.y + e2.z * pa.z + e2.w * pa.w);

            const float* sc = smScal + r * 16;
            float sav = sc[3], sal = sc[4], svl = sc[5];
            float sa = sc[6], sv = sc[7], sl = sc[8];
            float t0 = (sav + svl) / (d02 * i0 * i2 + 0.5f);   // savvl
            float t1 = (sav + sal) / (d01 * i0 * i1 + 0.5f);   // saavl
            float t2 = (sal + svl) / (d12 * i1 * i2 + 0.5f);   // savll
            float t3 = (sav + sl)  / (d0l * i0 + 0.5f);        // savl
            float t4 = (sal + sv)  / (d1v * i1 + 0.5f);        // salv
            float t5 = (sa  + svl) / (d2a * i2 + 0.5f);        // svla
            float mm = fmaxf(fmaxf(fmaxf(t0, t1), fmaxf(t2, t3)), fmaxf(t4, t5));
            float q0 = __expf(t0 - mm), q1 = __expf(t1 - mm), q2 = __expf(t2 - mm);
            float q3 = __expf(t3 - mm), q4 = __expf(t4 - mm), q5 = __expf(t5 - mm);
            float qi = 1.0f / (q0 + q1 + q2 + q3 + q4 + q5);
            if (lane == 0) {
                float* scw = smScal + r * 16;
                scw[9] = q0 * qi; scw[10] = q1 * qi; scw[11] = q2 * qi;
                scw[12] = q3 * qi; scw[13] = q4 * qi; scw[14] = q5 * qi;
            }

            float n0 = sc[0], n1 = sc[1], n2v = sc[2];
            float4 av = make_float4(tanh_fast(n0 * g0.x), tanh_fast(n0 * g0.y), tanh_fast(n0 * g0.z), tanh_fast(n0 * g0.w));
            float4 al = make_float4(tanh_fast(n1 * g1.x), tanh_fast(n1 * g1.y), tanh_fast(n1 * g1.z), tanh_fast(n1 * g1.w));
            float4 vl = make_float4(tanh_fast(n2v * g2.x), tanh_fast(n2v * g2.y), tanh_fast(n2v * g2.z), tanh_fast(n2v * g2.w));
            ((float4*)(smG + 0 * R * D + r * D))[lane] = av;
            ((float4*)(smG + 1 * R * D + r * D))[lane] = al;
            ((float4*)(smG + 2 * R * D + r * D))[lane] = vl;
            float4 bm = make_float4(av.x + al.x + vl.x, av.y + al.y + vl.y,
                                    av.z + al.z + vl.z, av.w + al.w + vl.w);
            ((float4*)(smFus + r * 384 + 128))[lane] = bm;              // bimodal
            ((float4*)(smFus + r * 384 + 256))[lane] = make_float4(0.f, 0.f, 0.f, 0.f);  // trimodal init
        }
    }
    __syncthreads();

    // ================= gf2 stages (trimodal) =================
    float* G0 = smG;               // a_v
    float* G1 = smG + R * D;       // a_l
    float* G2 = smG + 2 * R * D;   // v_l
    mlp_stage<1, 0>(gf2_w1, gf2_b1, gf2_w2, gf2_b2,
                    G0, G2, G0, G1, G2, G1,
                    smH, smG, smFus, smScal);
    __syncthreads();
    mlp_stage<1, 3>(gf2_w1, gf2_b1, gf2_w2, gf2_b2,
                    G0, smL, G1, smV, G2, smA,
                    smH, smG, smFus, smScal);
    __syncthreads();

    // ================= ll chain: fusion[32][384] -> 64 -> 64 -> 128 =================
    {
        // [32 x 384] @ [384 x 64]: 1 row x 4 cols per thread
        const int rg = tid >> 4, cg = tid & 15;
        float4 bb = __ldg((const float4*)(ll_b1 + cg * 4));
        float acc[4] = {bb.x, bb.y, bb.z, bb.w};
        const float4* x4 = (const float4*)(smFus + rg * 384);
#pragma unroll 2
        for (int k4 = 0; k4 < 96; ++k4) {
            const float* wb = ll_w1 + (k4 * 4) * 64 + cg * 4;
            float4 w0 = __ldg((const float4*)(wb));
            float4 w1 = __ldg((const float4*)(wb + 64));
            float4 w2 = __ldg((const float4*)(wb + 128));
            float4 w3 = __ldg((const float4*)(wb + 192));
            float4 x = x4[k4];
            acc[0] = fmaf(x.x, w0.x, acc[0]); acc[1] = fmaf(x.x, w0.y, acc[1]);
            acc[2] = fmaf(x.x, w0.z, acc[2]); acc[3] = fmaf(x.x, w0.w, acc[3]);
            acc[0] = fmaf(x.y, w1.x, acc[0]); acc[1] = fmaf(x.y, w1.y, acc[1]);
            acc[2] = fmaf(x.y, w1.z, acc[2]); acc[3] = fmaf(x.y, w1.w, acc[3]);
            acc[0] = fmaf(x.z, w2.x, acc[0]); acc[1] = fmaf(x.z, w2.y, acc[1]);
            acc[2] = fmaf(x.z, w2.z, acc[2]); acc[3] = fmaf(x.z, w2.w, acc[3]);
            acc[0] = fmaf(x.w, w3.x, acc[0]); acc[1] = fmaf(x.w, w3.y, acc[1]);
            acc[2] = fmaf(x.w, w3.z, acc[2]); acc[3] = fmaf(x.w, w3.w, acc[3]);
        }
#pragma unroll
        for (int j = 0; j < 4; ++j)
            smH[rg * 64 + cg * 4 + j] = tanh_fast(acc[j]);
    }
    __syncthreads();
    {
        // [32 x 64] @ [64 x 64]: 1 row x 4 cols per thread
        const int rg = tid >> 4, cg = tid & 15;
        float4 bb = __ldg((const float4*)(ll_b2 + cg * 4));
        float acc[4] = {bb.x, bb.y, bb.z, bb.w};
        const float4* x4 = (const float4*)(smH + rg * 64);
#pragma unroll 2
        for (int k4 = 0; k4 < 16; ++k4) {
            const float* wb = ll_w2 + (k4 * 4) * 64 + cg * 4;
            float4 w0 = __ldg((const float4*)(wb));
            float4 w1 = __ldg((const float4*)(wb + 64));
            float4 w2 = __ldg((const float4*)(wb + 128));
            float4 w3 = __ldg((const float4*)(wb + 192));
            float4 x = x4[k4];
            acc[0] = fmaf(x.x, w0.x, acc[0]); acc[1] = fmaf(x.x, w0.y, acc[1]);
            acc[2] = fmaf(x.x, w0.z, acc[2]); acc[3] = fmaf(x.x, w0.w, acc[3]);
            acc[0] = fmaf(x.y, w1.x, acc[0]); acc[1] = fmaf(x.y, w1.y, acc[1]);
            acc[2] = fmaf(x.y, w1.z, acc[2]); acc[3] = fmaf(x.y, w1.w, acc[3]);
            acc[0] = fmaf(x.z, w2.x, acc[0]); acc[1] = fmaf(x.z, w2.y, acc[1]);
            acc[2] = fmaf(x.z, w2.z, acc[2]); acc[3] = fmaf(x.z, w2.w, acc[3]);
            acc[0] = fmaf(x.w, w3.x, acc[0]); acc[1] = fmaf(x.w, w3.y, acc[1]);
            acc[2] = fmaf(x.w, w3.z, acc[2]); acc[3] = fmaf(x.w, w3.w, acc[3]);
        }
#pragma unroll
        for (int j = 0; j < 4; ++j)
            smH[2048 + rg * 64 + cg * 4 + j] = tanh_fast(acc[j]);  // H2 region
    }
    __syncthreads();
    {
        // [32 x 64] @ [64 x 128]: 2 rows x 4 cols per thread (accurate tanh on output)
        const int rg = tid >> 5, cg = tid & 31;
        float4 bb = __ldg((const float4*)(ll_b3 + cg * 4));
        float acc[2][4];
#pragma unroll
        for (int i = 0; i < 2; ++i) {
            acc[i][0] = bb.x; acc[i][1] = bb.y; acc[i][2] = bb.z; acc[i][3] = bb.w;
        }
        const float4* x40 = (const float4*)(smH + 2048 + (rg * 2) * 64);
        const float4* x41 = (const float4*)(smH + 2048 + (rg * 2 + 1) * 64);
#pragma unroll 2
        for (int k4 = 0; k4 < 16; ++k4) {
            const float* wb = ll_w3 + (k4 * 4) * 128 + cg * 4;
            float4 w0 = __ldg((const float4*)(wb));
            float4 w1 = __ldg((const float4*)(wb + 128));
            float4 w2 = __ldg((const float4*)(wb + 256));
            float4 w3 = __ldg((const float4*)(wb + 384));
            float4 x0 = x40[k4];
            float4 x1 = x41[k4];
            acc[0][0] = fmaf(x0.x, w0.x, acc[0][0]); acc[0][1] = fmaf(x0.x, w0.y, acc[0][1]);
            acc[0][2] = fmaf(x0.x, w0.z, acc[0][2]); acc[0][3] = fmaf(x0.x, w0.w, acc[0][3]);
            acc[0][0] = fmaf(x0.y, w1.x, acc[0][0]); acc[0][1] = fmaf(x0.y, w1.y, acc[0][1]);
            acc[0][2] = fmaf(x0.y, w1.z, acc[0][2]); acc[0][3] = fmaf(x0.y, w1.w, acc[0][3]);
            acc[0][0] = fmaf(x0.z, w2.x, acc[0][0]); acc[0][1] = fmaf(x0.z, w2.y, acc[0][1]);
            acc[0][2] = fmaf(x0.z, w2.z, acc[0][2]); acc[0][3] = fmaf(x0.z, w2.w, acc[0][3]);
            acc[0][0] = fmaf(x0.w, w3.x, acc[0][0]); acc[0][1] = fmaf(x0.w, w3.y, acc[0][1]);
            acc[0][2] = fmaf(x0.w, w3.z, acc[0][2]); acc[0][3] = fmaf(x0.w, w3.w, acc[0][3]);
            acc[1][0] = fmaf(x1.x, w0.x, acc[1][0]); acc[1][1] = fmaf(x1.x, w0.y, acc[1][1]);
            acc[1][2] = fmaf(x1.x, w0.z, acc[1][2]); acc[1][3] = fmaf(x1.x, w0.w, acc[1][3]);
            acc[1][0] = fmaf(x1.y, w1.x, acc[1][0]); acc[1][1] = fmaf(x1.y, w1.y, acc[1][1]);
            acc[1][2] = fmaf(x1.y, w1.z, acc[1][2]); acc[1][3] = fmaf(x1.y, w1.w, acc[1][3]);
            acc[1][0] = fmaf(x1.z, w2.x, acc[1][0]); acc[1][1] = fmaf(x1.z, w2.y, acc[1][1]);
            acc[1][2] = fmaf(x1.z, w2.z, acc[1][2]); acc[1][3] = fmaf(x1.z, w2.w, acc[1][3]);
            acc[1][0] = fmaf(x1.w, w3.x, acc[1][0]); acc[1][1] = fmaf(x1.w, w3.y, acc[1][1]);
            acc[1][2] = fmaf(x1.w, w3.z, acc[1][2]); acc[1][3] = fmaf(x1.w, w3.w, acc[1][3]);
        }
#pragma unroll
        for (int i = 0; i < 2; ++i) {
            int r = rg * 2 + i;
            size_t grow = (size_t)blockIdx.x * R + r;
            float4 o = make_float4(tanhf(acc[i][0]), tanhf(acc[i][1]), tanhf(acc[i][2]), tanhf(acc[i][3]));
            ((float4*)(out + grow * D))[cg] = o;
        }
    }
}

extern "C" void kernel_launch(void* const* d_in, const int* in_sizes, int n_in,
                              void* d_out, int out_size) {
    const float* Lm     = (const float*)d_in[0];
    const float* Am     = (const float*)d_in[1];
    const float* Vm     = (const float*)d_in[2];
    const float* att_w  = (const float*)d_in[3];
    const float* att_b  = (const float*)d_in[4];
    const float* gf_w1  = (const float*)d_in[5];
    const float* gf_b1  = (const float*)d_in[6];
    const float* gf_w2  = (const float*)d_in[7];
    const float* gf_b2  = (const float*)d_in[8];
    const float* gf2_w1 = (const float*)d_in[9];
    const float* gf2_b1 = (const float*)d_in[10];
    const float* gf2_w2 = (const float*)d_in[11];
    const float* gf2_b2 = (const float*)d_in[12];
    const float* ll_w1  = (const float*)d_in[13];
    const float* ll_b1  = (const float*)d_in[14];
    const float* ll_w2  = (const float*)d_in[15];
    const float* ll_b2  = (const float*)d_in[16];
    const float* ll_w3  = (const float*)d_in[17];
    const float* ll_b3  = (const float*)d_in[18];

    int nrows = in_sizes[0] / D;
    int grid = nrows / R;
    size_t smem = (size_t)SMEM_FLOATS * sizeof(float);
    cudaFuncSetAttribute(graphfusion_kernel,
                         cudaFuncAttributeMaxDynamicSharedMemorySize, (int)smem);
    graphfusion_kernel<<<grid, NTHREADS, smem>>>(
        Lm, Am, Vm, att_w, att_b,
        gf_w1, gf_b1, gf_w2, gf_b2,
        gf2_w1, gf2_b1, gf2_w2, gf2_b2,
        ll_w1, ll_b1, ll_w2, ll_b2, ll_w3, ll_b3,
        (float*)d_out);
}

// round 3
// speedup vs baseline: 1.7281x; 1.3525x over previous
#include <cuda_runtime.h>
#include <math.h>

typedef unsigned long long u64;

namespace {
constexpr int D = 128;
constexpr int R = 32;          // rows per block
constexpr int NT = 512;
constexpr int SA = 132;        // stride (floats) for [32][128] activation arrays (132%32==4 -> conflict-free f4)
constexpr int SF = 388;        // fusion stride
constexpr int SH = 68;         // H stride
constexpr int SR = 28;         // reduction scratch lane stride
constexpr int OFF_A   = 0;
constexpr int OFF_V   = OFF_A + R * SA;
constexpr int OFF_L   = OFF_V + R * SA;
constexpr int OFF_G0  = OFF_L + R * SA;
constexpr int OFF_G1  = OFF_G0 + R * SA;
constexpr int OFF_G2  = OFF_G1 + R * SA;
constexpr int OFF_FUS = OFF_G2 + R * SA;
constexpr int OFF_H   = OFF_FUS + R * SF;   // [96][SH]
constexpr int OFF_H2  = OFF_H + 96 * SH;    // [32][SH]
constexpr int OFF_RED = OFF_H2 + 32 * SH;   // [8][32][SR]
constexpr int OFF_AW  = OFF_RED + 8 * 32 * SR;
constexpr int OFF_SC  = OFF_AW + 128;
constexpr int SMEM_FLOATS = OFF_SC + R * 16;
}

__device__ __forceinline__ float warp_sum(float x) {
#pragma unroll
    for (int o = 16; o > 0; o >>= 1) x += __shfl_xor_sync(0xffffffffu, x, o);
    return x;
}
__device__ __forceinline__ float warp_max(float x) {
#pragma unroll
    for (int o = 16; o > 0; o >>= 1) x = fmaxf(x, __shfl_xor_sync(0xffffffffu, x, o));
    return x;
}
__device__ __forceinline__ float tanh_fast(float x) {
    float y;
    asm("tanh.approx.f32 %0, %1;" : "=f"(y) : "f"(x));
    return y;
}
// ---- packed f32x2 helpers ----
__device__ __forceinline__ u64 pk2(float lo, float hi) {
    u64 r; asm("mov.b64 %0, {%1, %2};" : "=l"(r) : "f"(lo), "f"(hi)); return r;
}
__device__ __forceinline__ u64 pkdup(float x) {
    u64 r; asm("mov.b64 %0, {%1, %1};" : "=l"(r) : "f"(x)); return r;
}
__device__ __forceinline__ void fma2(u64& d, u64 a, u64 b) {
    asm("fma.rn.f32x2 %0, %1, %2, %0;" : "+l"(d) : "l"(a), "l"(b));
}
__device__ __forceinline__ void add2(u64& d, u64 a) {
    asm("add.rn.f32x2 %0, %0, %1;" : "+l"(d) : "l"(a));
}
__device__ __forceinline__ float2 up2(u64 v) {
    float2 f; asm("mov.b64 {%0, %1}, %2;" : "=f"(f.x), "=f"(f.y) : "l"(v)); return f;
}
__device__ __forceinline__ float xcomp(const float4& v, int kk) {
    return (kk == 0) ? v.x : (kk == 1) ? v.y : (kk == 2) ? v.z : v.w;
}

// gf-style MLP over 3 row-pairs (96 rows):
//   H = leaky_relu(concat(x,y) @ W1 + b1); G = tanh(H @ W2 + b2)
// Warp layout GEMM1: h=wid>>3 selects k-half (x vs y), wq=wid&7 owns cols 8wq..8wq+7,
// lane l owns rows {l, l+32, l+64} (one per pair). k-halves reduced via smRed.
// GEMM2: all 16 warps own 8 cols each (128 cols), same lane->rows map.
// MODE 0: G -> smG[p]. MODE 1: smFus[l][256+c] += sum_p tanh(n2[p]*G_p) (exclusive, no atomics)
template <int MODE, int N2BASE>
__device__ __forceinline__ void mlp_stage(
    const float* __restrict__ W1, const float* __restrict__ b1,
    const float* __restrict__ W2, const float* __restrict__ b2,
    const float* x0, const float* x1, const float* x2,
    const float* y0, const float* y1, const float* y2,
    float* sm)
{
    const int tid = threadIdx.x;
    const int l   = tid & 31;
    const int wid = tid >> 5;
    const int h   = wid >> 3;
    const int wq  = wid & 7;
    float* smH   = sm + OFF_H;
    float* smRed = sm + OFF_RED;

    // ---------------- GEMM1 partial over this k-half ----------------
    u64 acc[3][4];
#pragma unroll
    for (int i = 0; i < 3; ++i)
#pragma unroll
        for (int j = 0; j < 4; ++j) acc[i][j] = 0ull;

    const float* s0 = h ? y0 : x0;
    const float* s1 = h ? y1 : x1;
    const float* s2 = h ? y2 : x2;
    const float4* xf[3] = { (const float4*)(s0 + l * SA),
                            (const float4*)(s1 + l * SA),
                            (const float4*)(s2 + l * SA) };
    const float* W1b = W1 + h * 128 * 64 + wq * 8;
#pragma unroll 2
    for (int k4 = 0; k4 < 32; ++k4) {
        float4 xv[3];
#pragma unroll
        for (int i = 0; i < 3; ++i) xv[i] = xf[i][k4];
#pragma unroll
        for (int kk = 0; kk < 4; ++kk) {
            const float* wr = W1b + (k4 * 4 + kk) * 64;
            ulonglong2 wa = __ldg((const ulonglong2*)wr);
            ulonglong2 wb = __ldg((const ulonglong2*)(wr + 4));
#pragma unroll
            for (int i = 0; i < 3; ++i) {
                u64 xx = pkdup(xcomp(xv[i], kk));
                fma2(acc[i][0], wa.x, xx);
                fma2(acc[i][1], wa.y, xx);
                fma2(acc[i][2], wb.x, xx);
                fma2(acc[i][3], wb.y, xx);
            }
        }
    }
    // ---------------- cross-half reduction + H epilogue ----------------
    float* rb = smRed + (wq * 32 + l) * SR;
    if (h) {
#pragma unroll
        for (int i = 0; i < 3; ++i) {
            ((ulonglong2*)(rb + i * 8))[0]     = make_ulonglong2(acc[i][0], acc[i][1]);
            ((ulonglong2*)(rb + i * 8 + 4))[0] = make_ulonglong2(acc[i][2], acc[i][3]);
        }
    }
    __syncthreads();
    if (!h) {
        const int col0 = wq * 8;
        float4 bb0 = __ldg((const float4*)(b1 + col0));
        float4 bb1 = __ldg((const float4*)(b1 + col0 + 4));
        float bias[8] = {bb0.x, bb0.y, bb0.z, bb0.w, bb1.x, bb1.y, bb1.z, bb1.w};
#pragma unroll
        for (int i = 0; i < 3; ++i) {
            ulonglong2 ra = ((const ulonglong2*)(rb + i * 8))[0];
            ulonglong2 rc = ((const ulonglong2*)(rb + i * 8 + 4))[0];
            add2(acc[i][0], ra.x); add2(acc[i][1], ra.y);
            add2(acc[i][2], rc.x); add2(acc[i][3], rc.y);
            float hv[8];
#pragma unroll
            for (int j = 0; j < 4; ++j) {
                float2 f = up2(acc[i][j]);
                hv[2 * j] = f.x; hv[2 * j + 1] = f.y;
            }
#pragma unroll
            for (int j = 0; j < 8; ++j) {
                float t = hv[j] + bias[j];
                hv[j] = (t >= 0.0f) ? t : 0.2f * t;
            }
            float* hp = smH + (l + 32 * i) * SH + col0;
            ((float4*)hp)[0]       = make_float4(hv[0], hv[1], hv[2], hv[3]);
            ((float4*)(hp + 4))[0] = make_float4(hv[4], hv[5], hv[6], hv[7]);
        }
    }
    __syncthreads();
    // ---------------- GEMM2: [96x64] @ [64x128] ----------------
    {
        const int col0 = wid * 8;
        float4 b20 = __ldg((const float4*)(b2 + col0));
        float4 b21 = __ldg((const float4*)(b2 + col0 + 4));
        u64 g[3][4];
#pragma unroll
        for (int i = 0; i < 3; ++i) {
            g[i][0] = pk2(b20.x, b20.y); g[i][1] = pk2(b20.z, b20.w);
            g[i][2] = pk2(b21.x, b21.y); g[i][3] = pk2(b21.z, b21.w);
        }
        const float4* hf[3] = { (const float4*)(smH + l * SH),
                                (const float4*)(smH + (l + 32) * SH),
                                (const float4*)(smH + (l + 64) * SH) };
        const float* W2b = W2 + col0;
#pragma unroll 2
        for (int k4 = 0; k4 < 16; ++k4) {
            float4 xv[3];
#pragma unroll
            for (int i = 0; i < 3; ++i) xv[i] = hf[i][k4];
#pragma unroll
            for (int kk = 0; kk < 4; ++kk) {
                const float* wr = W2b + (k4 * 4 + kk) * 128;
                ulonglong2 wa = __ldg((const ulonglong2*)wr);
                ulonglong2 wb = __ldg((const ulonglong2*)(wr + 4));
#pragma unroll
                for (int i = 0; i < 3; ++i) {
                    u64 xx = pkdup(xcomp(xv[i], kk));
                    fma2(g[i][0], wa.x, xx);
                    fma2(g[i][1], wa.y, xx);
                    fma2(g[i][2], wb.x, xx);
                    fma2(g[i][3], wb.y, xx);
                }
            }
        }
        float gv[3][8];
#pragma unroll
        for (int i = 0; i < 3; ++i)
#pragma unroll
            for (int j = 0; j < 4; ++j) {
                float2 f = up2(g[i][j]);
                gv[i][2 * j] = f.x; gv[i][2 * j + 1] = f.y;
            }
        if (MODE == 0) {
#pragma unroll
            for (int i = 0; i < 3; ++i) {
                float* gp = sm + ((i == 0) ? OFF_G0 : (i == 1) ? OFF_G1 : OFF_G2) + l * SA + col0;
                ((float4*)gp)[0]       = make_float4(tanh_fast(gv[i][0]), tanh_fast(gv[i][1]),
                                                     tanh_fast(gv[i][2]), tanh_fast(gv[i][3]));
                ((float4*)(gp + 4))[0] = make_float4(tanh_fast(gv[i][4]), tanh_fast(gv[i][5]),
                                                     tanh_fast(gv[i][6]), tanh_fast(gv[i][7]));
            }
        } else {
            const float* sc = sm + OFF_SC + l * 16;
            float nv0 = sc[9 + N2BASE + 0];
            float nv1 = sc[9 + N2BASE + 1];
            float nv2 = sc[9 + N2BASE + 2];
            float s[8];
#pragma unroll
            for (int j = 0; j < 8; ++j)
                s[j] = tanh_fast(nv0 * tanh_fast(gv[0][j]))
                     + tanh_fast(nv1 * tanh_fast(gv[1][j]))
                     + tanh_fast(nv2 * tanh_fast(gv[2][j]));
            float* fp = sm + OFF_FUS + l * SF + 256 + col0;
            float4 f0 = ((float4*)fp)[0];
            float4 f1 = ((float4*)(fp + 4))[0];
            f0.x += s[0]; f0.y += s[1]; f0.z += s[2]; f0.w += s[3];
            f1.x += s[4]; f1.y += s[5]; f1.z += s[6]; f1.w += s[7];
            ((float4*)fp)[0] = f0;
            ((float4*)(fp + 4))[0] = f1;
        }
    }
}

__global__ void __launch_bounds__(NT, 1)
graphfusion_kernel(
    const float* __restrict__ Lm, const float* __restrict__ Am, const float* __restrict__ Vm,
    const float* __restrict__ att_w, const float* __restrict__ att_b,
    const float* __restrict__ gf_w1, const float* __restrict__ gf_b1,
    const float* __restrict__ gf_w2, const float* __restrict__ gf_b2,
    const float* __restrict__ gf2_w1, const float* __restrict__ gf2_b1,
    const float* __restrict__ gf2_w2, const float* __restrict__ gf2_b2,
    const float* __restrict__ ll_w1, const float* __restrict__ ll_b1,
    const float* __restrict__ ll_w2, const float* __restrict__ ll_b2,
    const float* __restrict__ ll_w3, const float* __restrict__ ll_b3,
    float* __restrict__ out)
{
    extern __shared__ float sm[];
    float* smA   = sm + OFF_A;
    float* smV   = sm + OFF_V;
    float* smL   = sm + OFF_L;
    float* smFus = sm + OFF_FUS;
    float* smAttw = sm + OFF_AW;
    float* smScal = sm + OFF_SC;

    const int tid = threadIdx.x;
    const int lane = tid & 31;
    const int wid = tid >> 5;

    if (tid < D) smAttw[tid] = att_w[tid];
    __syncthreads();
    const float attb = __ldg(att_b);

    // ================= Phase A: scalars + softmaxes + unimodal =================
    {
        float4 aw = ((const float4*)smAttw)[lane];
#pragma unroll
        for (int rr = 0; rr < 2; ++rr) {
            int r = wid * 2 + rr;
            size_t grow = (size_t)blockIdx.x * R + r;
            float4 a4 = ((const float4*)(Am + grow * D))[lane];
            float4 v4 = ((const float4*)(Vm + grow * D))[lane];
            float4 l4 = ((const float4*)(Lm + grow * D))[lane];

            float sa = tanh_fast(warp_sum(a4.x * aw.x + a4.y * aw.y + a4.z * aw.z + a4.w * aw.w) + attb);
            float sv = tanh_fast(warp_sum(v4.x * aw.x + v4.y * aw.y + v4.z * aw.z + v4.w * aw.w) + attb);
            float sl = tanh_fast(warp_sum(l4.x * aw.x + l4.y * aw.y + l4.z * aw.z + l4.w * aw.w) + attb);

            float4 u;
            u.x = (sa * a4.x + sv * v4.x + sl * l4.x) * (1.0f / 3.0f);
            u.y = (sa * a4.y + sv * v4.y + sl * l4.y) * (1.0f / 3.0f);
            u.z = (sa * a4.z + sv * v4.z + sl * l4.z) * (1.0f / 3.0f);
            u.w = (sa * a4.w + sv * v4.w + sl * l4.w) * (1.0f / 3.0f);
            ((float4*)(smFus + r * SF))[lane] = u;

            float ma = warp_max(fmaxf(fmaxf(a4.x, a4.y), fmaxf(a4.z, a4.w)));
            float4 ea = make_float4(__expf(a4.x - ma), __expf(a4.y - ma), __expf(a4.z - ma), __expf(a4.w - ma));
            float ia = 1.0f / warp_sum(ea.x + ea.y + ea.z + ea.w);
            float4 pa = make_float4(ea.x * ia, ea.y * ia, ea.z * ia, ea.w * ia);

            float mv = warp_max(fmaxf(fmaxf(v4.x, v4.y), fmaxf(v4.z, v4.w)));
            float4 ev = make_float4(__expf(v4.x - mv), __expf(v4.y - mv), __expf(v4.z - mv), __expf(v4.w - mv));
            float iv = 1.0f / warp_sum(ev.x + ev.y + ev.z + ev.w);
            float4 pv = make_float4(ev.x * iv, ev.y * iv, ev.z * iv, ev.w * iv);

            float ml = warp_max(fmaxf(fmaxf(l4.x, l4.y), fmaxf(l4.z, l4.w)));
            float4 el = make_float4(__expf(l4.x - ml), __expf(l4.y - ml), __expf(l4.z - ml), __expf(l4.w - ml));
            float il = 1.0f / warp_sum(el.x + el.y + el.z + el.w);
            float4 pl = make_float4(el.x * il, el.y * il, el.z * il, el.w * il);

            ((float4*)(smA + r * SA))[lane] = pa;
            ((float4*)(smV + r * SA))[lane] = pv;
            ((float4*)(smL + r * SA))[lane] = pl;

            float dav = warp_sum(pa.x * pv.x + pa.y * pv.y + pa.z * pv.z + pa.w * pv.w);
            float dal = warp_sum(pa.x * pl.x + pa.y * pl.y + pa.z * pl.z + pa.w * pl.w);
            float dvl = warp_sum(pv.x * pl.x + pv.y * pl.y + pv.z * pl.z + pv.w * pl.w);

            float sav = (sa + sv) / (dav + 0.5f);
            float sal = (sa + sl) / (dal + 0.5f);
            float svl = (sl + sv) / (dvl + 0.5f);
            float mx = fmaxf(sav, fmaxf(sal, svl));
            float e0 = __expf(sav - mx), e1 = __expf(sal - mx), e2 = __expf(svl - mx);
            float is = 1.0f / (e0 + e1 + e2);
            if (lane == 0) {
                float* sc = smScal + r * 16;
                sc[0] = e0 * is; sc[1] = e1 * is; sc[2] = e2 * is;
                sc[3] = sav; sc[4] = sal; sc[5] = svl;
                sc[6] = sa;  sc[7] = sv;  sc[8] = sl;
            }
        }
    }
    __syncthreads();

    // ================= gf stage =================
    mlp_stage<0, 0>(gf_w1, gf_b1, gf_w2, gf_b2,
                    smA, smA, smV,       // x of pairs (a,v) (a,l) (v,l)
                    smV, smL, smL,       // y of pairs
                    sm);
    __syncthreads();

    // ============ Phase C ============
    {
#pragma unroll
        for (int rr = 0; rr < 2; ++rr) {
            int r = wid * 2 + rr;
            float4 g0 = ((const float4*)(sm + OFF_G0 + r * SA))[lane];
            float4 g1 = ((const float4*)(sm + OFF_G1 + r * SA))[lane];
            float4 g2 = ((const float4*)(sm + OFF_G2 + r * SA))[lane];
            float4 pa = ((const float4*)(smA + r * SA))[lane];
            float4 pv = ((const float4*)(smV + r * SA))[lane];
            float4 pl = ((const float4*)(smL + r * SA))[lane];

            float m0 = warp_max(fmaxf(fmaxf(g0.x, g0.y), fmaxf(g0.z, g0.w)));
            float m1 = warp_max(fmaxf(fmaxf(g1.x, g1.y), fmaxf(g1.z, g1.w)));
            float m2 = warp_max(fmaxf(fmaxf(g2.x, g2.y), fmaxf(g2.z, g2.w)));
            float4 e0 = make_float4(__expf(g0.x - m0), __expf(g0.y - m0), __expf(g0.z - m0), __expf(g0.w - m0));
            float4 e1 = make_float4(__expf(g1.x - m1), __expf(g1.y - m1), __expf(g1.z - m1), __expf(g1.w - m1));
            float4 e2 = make_float4(__expf(g2.x - m2), __expf(g2.y - m2), __expf(g2.z - m2), __expf(g2.w - m2));
            float i0 = 1.0f / warp_sum(e0.x + e0.y + e0.z + e0.w);
            float i1 = 1.0f / warp_sum(e1.x + e1.y + e1.z + e1.w);
            float i2 = 1.0f / warp_sum(e2.x + e2.y + e2.z + e2.w);

            float d01 = warp_sum(e0.x * e1.x + e0.y * e1.y + e0.z * e1.z + e0.w * e1.w);
            float d02 = warp_sum(e0.x * e2.x + e0.y * e2.y + e0.z * e2.z + e0.w * e2.w);
            float d12 = warp_sum(e1.x * e2.x + e1.y * e2.y + e1.z * e2.z + e1.w * e2.w);
            float d0l = warp_sum(e0.x * pl.x + e0.y * pl.y + e0.z * pl.z + e0.w * pl.w);
            float d1v = warp_sum(e1.x * pv.x + e1.y * pv.y + e1.z * pv.z + e1.w * pv.w);
            float d2a = warp_sum(e2.x * pa.x + e2.y * pa.y + e2.z * pa.z + e2.w * pa.w);

            const float* sc = smScal + r * 16;
            float sav = sc[3], sal = sc[4], svl = sc[5];
            float sa = sc[6], sv = sc[7], sl = sc[8];
            float t0 = (sav + svl) / (d02 * i0 * i2 + 0.5f);
            float t1 = (sav + sal) / (d01 * i0 * i1 + 0.5f);
            float t2 = (sal + svl) / (d12 * i1 * i2 + 0.5f);
            float t3 = (sav + sl)  / (d0l * i0 + 0.5f);
            float t4 = (sal + sv)  / (d1v * i1 + 0.5f);
            float t5 = (sa  + svl) / (d2a * i2 + 0.5f);
            float mm = fmaxf(fmaxf(fmaxf(t0, t1), fmaxf(t2, t3)), fmaxf(t4, t5));
            float q0 = __expf(t0 - mm), q1 = __expf(t1 - mm), q2 = __expf(t2 - mm);
            float q3 = __expf(t3 - mm), q4 = __expf(t4 - mm), q5 = __expf(t5 - mm);
            float qi = 1.0f / (q0 + q1 + q2 + q3 + q4 + q5);
            if (lane == 0) {
                float* scw = smScal + r * 16;
                scw[9] = q0 * qi; scw[10] = q1 * qi; scw[11] = q2 * qi;
                scw[12] = q3 * qi; scw[13] = q4 * qi; scw[14] = q5 * qi;
            }

            float n0 = sc[0], n1 = sc[1], n2v = sc[2];
            float4 av = make_float4(tanh_fast(n0 * g0.x), tanh_fast(n0 * g0.y), tanh_fast(n0 * g0.z), tanh_fast(n0 * g0.w));
            float4 al = make_float4(tanh_fast(n1 * g1.x), tanh_fast(n1 * g1.y), tanh_fast(n1 * g1.z), tanh_fast(n1 * g1.w));
            float4 vl = make_float4(tanh_fast(n2v * g2.x), tanh_fast(n2v * g2.y), tanh_fast(n2v * g2.z), tanh_fast(n2v * g2.w));
            ((float4*)(sm + OFF_G0 + r * SA))[lane] = av;
            ((float4*)(sm + OFF_G1 + r * SA))[lane] = al;
            ((float4*)(sm + OFF_G2 + r * SA))[lane] = vl;
            float4 bm = make_float4(av.x + al.x + vl.x, av.y + al.y + vl.y,
                                    av.z + al.z + vl.z, av.w + al.w + vl.w);
            ((float4*)(smFus + r * SF + 128))[lane] = bm;
            ((float4*)(smFus + r * SF + 256))[lane] = make_float4(0.f, 0.f, 0.f, 0.f);
        }
    }
    __syncthreads();

    // ================= gf2 stages (trimodal) =================
    float* G0 = sm + OFF_G0;   // a_v
    float* G1 = sm + OFF_G1;   // a_l
    float* G2 = sm + OFF_G2;   // v_l
    mlp_stage<1, 0>(gf2_w1, gf2_b1, gf2_w2, gf2_b2,
                    G0, G0, G2,          // x of (a_v,v_l) (a_v,a_l) (v_l,a_l)
                    G2, G1, G1,
                    sm);
    __syncthreads();
    mlp_stage<1, 3>(gf2_w1, gf2_b1, gf2_w2, gf2_b2,
                    G0, G1, G2,          // x of (a_v,l) (a_l,v) (v_l,a)
                    smL, smV, smA,
                    sm);
    __syncthreads();

    // ================= ll chain =================
    const int l = lane;
    // ll1: [32 x 384] @ [384 x 64], 8 col-groups x 2 k-halves
    {
        const int h2 = wid >> 3, wq = wid & 7, col0 = wq * 8;
        u64 acc[4] = {0ull, 0ull, 0ull, 0ull};
        const float4* xf = (const float4*)(sm + OFF_FUS + l * SF);
        const float* Wb = ll_w1 + h2 * 192 * 64 + col0;
#pragma unroll 2
        for (int k4 = 0; k4 < 48; ++k4) {
            float4 x = xf[h2 * 48 + k4];
#pragma unroll
            for (int kk = 0; kk < 4; ++kk) {
                const float* wr = Wb + (k4 * 4 + kk) * 64;
                ulonglong2 wa = __ldg((const ulonglong2*)wr);
                ulonglong2 wb = __ldg((const ulonglong2*)(wr + 4));
                u64 xx = pkdup(xcomp(x, kk));
                fma2(acc[0], wa.x, xx); fma2(acc[1], wa.y, xx);
                fma2(acc[2], wb.x, xx); fma2(acc[3], wb.y, xx);
            }
        }
        float* rb = sm + OFF_RED + (wq * 32 + l) * SR;
        if (h2) {
            ((ulonglong2*)rb)[0]       = make_ulonglong2(acc[0], acc[1]);
            ((ulonglong2*)(rb + 4))[0] = make_ulonglong2(acc[2], acc[3]);
        }
        __syncthreads();
        if (!h2) {
            ulonglong2 ra = ((const ulonglong2*)rb)[0];
            ulonglong2 rc = ((const ulonglong2*)(rb + 4))[0];
            add2(acc[0], ra.x); add2(acc[1], ra.y);
            add2(acc[2], rc.x); add2(acc[3], rc.y);
            float4 bb0 = __ldg((const float4*)(ll_b1 + col0));
            float4 bb1 = __ldg((const float4*)(ll_b1 + col0 + 4));
            float2 f0 = up2(acc[0]), f1 = up2(acc[1]), f2 = up2(acc[2]), f3 = up2(acc[3]);
            float* hp = sm + OFF_H2 + l * SH + col0;
            ((float4*)hp)[0] = make_float4(tanh_fast(f0.x + bb0.x), tanh_fast(f0.y + bb0.y),
                                           tanh_fast(f1.x + bb0.z), tanh_fast(f1.y + bb0.w));
            ((float4*)(hp + 4))[0] = make_float4(tanh_fast(f2.x + bb1.x), tanh_fast(f2.y + bb1.y),
                                                 tanh_fast(f3.x + bb1.z), tanh_fast(f3.y + bb1.w));
        }
        __syncthreads();
    }
    // ll2: [32 x 64] @ [64 x 64], 8 col-groups x 2 k-halves
    {
        const int h2 = wid >> 3, wq = wid & 7, col0 = wq * 8;
        u64 acc[4] = {0ull, 0ull, 0ull, 0ull};
        const float4* xf = (const float4*)(sm + OFF_H2 + l * SH);
        const float* Wb = ll_w2 + h2 * 32 * 64 + col0;
#pragma unroll
        for (int k4 = 0; k4 < 8; ++k4) {
            float4 x = xf[h2 * 8 + k4];
#pragma unroll
            for (int kk = 0; kk < 4; ++kk) {
                const float* wr = Wb + (k4 * 4 + kk) * 64;
                ulonglong2 wa = __ldg((const ulonglong2*)wr);
                ulonglong2 wb = __ldg((const ulonglong2*)(wr + 4));
                u64 xx = pkdup(xcomp(x, kk));
                fma2(acc[0], wa.x, xx); fma2(acc[1], wa.y, xx);
                fma2(acc[2], wb.x, xx); fma2(acc[3], wb.y, xx);
            }
        }
        float* rb = sm + OFF_RED + (wq * 32 + l) * SR;
        if (h2) {
            ((ulonglong2*)rb)[0]       = make_ulonglong2(acc[0], acc[1]);
            ((ulonglong2*)(rb + 4))[0] = make_ulonglong2(acc[2], acc[3]);
        }
        __syncthreads();
        if (!h2) {
            ulonglong2 ra = ((const ulonglong2*)rb)[0];
            ulonglong2 rc = ((const ulonglong2*)(rb + 4))[0];
            add2(acc[0], ra.x); add2(acc[1], ra.y);
            add2(acc[2], rc.x); add2(acc[3], rc.y);
            float4 bb0 = __ldg((const float4*)(ll_b2 + col0));
            float4 bb1 = __ldg((const float4*)(ll_b2 + col0 + 4));
            float2 f0 = up2(acc[0]), f1 = up2(acc[1]), f2 = up2(acc[2]), f3 = up2(acc[3]);
            float* hp = sm + OFF_H + l * SH + col0;   // reuse H rows 0-31
            ((float4*)hp)[0] = make_float4(tanh_fast(f0.x + bb0.x), tanh_fast(f0.y + bb0.y),
                                           tanh_fast(f1.x + bb0.z), tanh_fast(f1.y + bb0.w));
            ((float4*)(hp + 4))[0] = make_float4(tanh_fast(f2.x + bb1.x), tanh_fast(f2.y + bb1.y),
                                                 tanh_fast(f3.x + bb1.z), tanh_fast(f3.y + bb1.w));
        }
        __syncthreads();
    }
    // ll3: [32 x 64] @ [64 x 128], 16 col-groups, full k, accurate tanh
    {
        const int col0 = wid * 8;
        u64 acc[4] = {0ull, 0ull, 0ull, 0ull};
        const float4* xf = (const float4*)(sm + OFF_H + l * SH);
        const float* Wb = ll_w3 + col0;
#pragma unroll 2
        for (int k4 = 0; k4 < 16; ++k4) {
            float4 x = xf[k4];
#pragma unroll
            for (int kk = 0; kk < 4; ++kk) {
                const float* wr = Wb + (k4 * 4 + kk) * 128;
                ulonglong2 wa = __ldg((const ulonglong2*)wr);
                ulonglong2 wb = __ldg((const ulonglong2*)(wr + 4));
                u64 xx = pkdup(xcomp(x, kk));
                fma2(acc[0], wa.x, xx); fma2(acc[1], wa.y, xx);
                fma2(acc[2], wb.x, xx); fma2(acc[3], wb.y, xx);
            }
        }
        float4 bb0 = __ldg((const float4*)(ll_b3 + col0));
        float4 bb1 = __ldg((const float4*)(ll_b3 + col0 + 4));
        float2 f0 = up2(acc[0]), f1 = up2(acc[1]), f2 = up2(acc[2]), f3 = up2(acc[3]);
        float* op = out + ((size_t)blockIdx.x * R + l) * D + col0;
        ((float4*)op)[0] = make_float4(tanhf(f0.x + bb0.x), tanhf(f0.y + bb0.y),
                                       tanhf(f1.x + bb0.z), tanhf(f1.y + bb0.w));
        ((float4*)(op + 4))[0] = make_float4(tanhf(f2.x + bb1.x), tanhf(f2.y + bb1.y),
                                             tanhf(f3.x + bb1.z), tanhf(f3.y + bb1.w));
    }
}

extern "C" void kernel_launch(void* const* d_in, const int* in_sizes, int n_in,
                              void* d_out, int out_size) {
    const float* Lm     = (const float*)d_in[0];
    const float* Am     = (const float*)d_in[1];
    const float* Vm     = (const float*)d_in[2];
    const float* att_w  = (const float*)d_in[3];
    const float* att_b  = (const float*)d_in[4];
    const float* gf_w1  = (const float*)d_in[5];
    const float* gf_b1  = (const float*)d_in[6];
    const float* gf_w2  = (const float*)d_in[7];
    const float* gf_b2  = (const float*)d_in[8];
    const float* gf2_w1 = (const float*)d_in[9];
    const float* gf2_b1 = (const float*)d_in[10];
    const float* gf2_w2 = (const float*)d_in[11];
    const float* gf2_b2 = (const float*)d_in[12];
    const float* ll_w1  = (const float*)d_in[13];
    const float* ll_b1  = (const float*)d_in[14];
    const float* ll_w2  = (const float*)d_in[15];
    const float* ll_b2  = (const float*)d_in[16];
    const float* ll_w3  = (const float*)d_in[17];
    const float* ll_b3  = (const float*)d_in[18];

    int nrows = in_sizes[0] / D;
    int grid = nrows / R;
    size_t smem = (size_t)SMEM_FLOATS * sizeof(float);
    cudaFuncSetAttribute(graphfusion_kernel,
                         cudaFuncAttributeMaxDynamicSharedMemorySize, (int)smem);
    graphfusion_kernel<<<grid, NT, smem>>>(
        Lm, Am, Vm, att_w, att_b,
        gf_w1, gf_b1, gf_w2, gf_b2,
        gf2_w1, gf2_b1, gf2_w2, gf2_b2,
        ll_w1, ll_b1, ll_w2, ll_b2, ll_w3, ll_b3,
        (float*)d_out);
}